// round 11
// baseline (speedup 1.0000x reference)
#include <cuda_runtime.h>
#include <cuda_bf16.h>
#include <cstdint>

// Problem constants
#define T_STEPS  4
#define P_DIM    63
#define D_DIM    128
#define BN_ROWS  65536              // B*N = 64*1024
#define M_TOTAL  262144             // T*B*N
#define N_TILES  4096               // M_TOTAL / 64

// ---------------------------------------------------------------------------
// Scratch (no allocations allowed -> __device__ globals)
// ---------------------------------------------------------------------------
__device__ double g_C[64 * 64];     // S = sum_m x_m x_m^T  (col 63 zero-padded)
__device__ double g_colsum[64];     // per-feature column sums of x
__device__ float4 g_prm[D_DIM];     // per-channel (mean, rsqrt(var+eps), gamma, beta)
// 2-way bf16 split of x, layout [M_TOTAL][64] (k=63 zero-padded), k contiguous
__device__ __nv_bfloat16 g_xh[(size_t)M_TOTAL * 64];
__device__ __nv_bfloat16 g_xl[(size_t)M_TOTAL * 64];

__device__ __forceinline__ uint16_t bfbits(float v) {
    __nv_bfloat16 b = __float2bfloat16_rn(v);
    return *reinterpret_cast<uint16_t*>(&b);
}
__device__ __forceinline__ float bf2f(uint16_t u) {
    __nv_bfloat16 b = *reinterpret_cast<__nv_bfloat16*>(&u);
    return __bfloat162float(b);
}

// ---------------------------------------------------------------------------
// Kernel 0: zero the stat accumulators (graph replays -> every launch)
// ---------------------------------------------------------------------------
__global__ void zero_stats_kernel() {
    int i = blockIdx.x * blockDim.x + threadIdx.x;
    if (i < 64 * 64) g_C[i] = 0.0;
    if (i < 64)      g_colsum[i] = 0.0;
}

// ---------------------------------------------------------------------------
// Kernel 1: stats pass.  S += X^T X, colsum += X^T 1, AND emit the 2-way bf16
// split of x into g_xh/g_xl. (unchanged from round 10, known good)
// ---------------------------------------------------------------------------
__global__ __launch_bounds__(256) void stats_kernel(const float* __restrict__ x) {
    __shared__ __align__(16) float xs[64][64];
    const int tid = threadIdx.x;
    const int ti = tid >> 4;
    const int tj = tid & 15;
    const int col = tid & 63;
    const int rg  = tid >> 6;

    float c00=0.f,c01=0.f,c02=0.f,c03=0.f;
    float c10=0.f,c11=0.f,c12=0.f,c13=0.f;
    float c20=0.f,c21=0.f,c22=0.f,c23=0.f;
    float c30=0.f,c31=0.f,c32=0.f,c33=0.f;
    float csum = 0.f;

    for (int tile = blockIdx.x; tile < N_TILES; tile += gridDim.x) {
        __syncthreads();
        const float* xb = x + (size_t)tile * (64 * 63);
        for (int i2 = tid; i2 < 64 * 64; i2 += 256) {
            int r = i2 >> 6, cc = i2 & 63;
            xs[r][cc] = (cc < 63) ? xb[r * 63 + cc] : 0.f;
        }
        __syncthreads();

        // emit bf16 2-way split (packed u32 = two consecutive k)
        {
            uint32_t* xh32 = (uint32_t*)g_xh + (size_t)tile * (64 * 32);
            uint32_t* xl32 = (uint32_t*)g_xl + (size_t)tile * (64 * 32);
            for (int i2 = tid; i2 < 64 * 32; i2 += 256) {
                int r = i2 >> 5, cp = i2 & 31;
                float f0 = xs[r][2 * cp], f1 = xs[r][2 * cp + 1];
                uint16_t h0 = bfbits(f0);
                uint16_t l0 = bfbits(f0 - bf2f(h0));
                uint16_t h1 = bfbits(f1);
                uint16_t l1 = bfbits(f1 - bf2f(h1));
                xh32[r * 32 + cp] = ((uint32_t)h1 << 16) | h0;
                xl32[r * 32 + cp] = ((uint32_t)l1 << 16) | l0;
            }
        }

        #pragma unroll 4
        for (int r = rg; r < 64; r += 4) csum += xs[r][col];

        #pragma unroll 4
        for (int r = 0; r < 64; r++) {
            float4 a = *(const float4*)&xs[r][4 * ti];
            float4 b = *(const float4*)&xs[r][4 * tj];
            c00 = fmaf(a.x, b.x, c00); c01 = fmaf(a.x, b.y, c01);
            c02 = fmaf(a.x, b.z, c02); c03 = fmaf(a.x, b.w, c03);
            c10 = fmaf(a.y, b.x, c10); c11 = fmaf(a.y, b.y, c11);
            c12 = fmaf(a.y, b.z, c12); c13 = fmaf(a.y, b.w, c13);
            c20 = fmaf(a.z, b.x, c20); c21 = fmaf(a.z, b.y, c21);
            c22 = fmaf(a.z, b.z, c22); c23 = fmaf(a.z, b.w, c23);
            c30 = fmaf(a.w, b.x, c30); c31 = fmaf(a.w, b.y, c31);
            c32 = fmaf(a.w, b.z, c32); c33 = fmaf(a.w, b.w, c33);
        }
    }

    __syncthreads();
    xs[rg][col] = csum;
    __syncthreads();
    if (tid < 64) {
        float s = xs[0][tid] + xs[1][tid] + xs[2][tid] + xs[3][tid];
        atomicAdd(&g_colsum[tid], (double)s);
    }

    const int rbase = 4 * ti, cbase = 4 * tj;
    atomicAdd(&g_C[(rbase+0)*64 + cbase+0], (double)c00);
    atomicAdd(&g_C[(rbase+0)*64 + cbase+1], (double)c01);
    atomicAdd(&g_C[(rbase+0)*64 + cbase+2], (double)c02);
    atomicAdd(&g_C[(rbase+0)*64 + cbase+3], (double)c03);
    atomicAdd(&g_C[(rbase+1)*64 + cbase+0], (double)c10);
    atomicAdd(&g_C[(rbase+1)*64 + cbase+1], (double)c11);
    atomicAdd(&g_C[(rbase+1)*64 + cbase+2], (double)c12);
    atomicAdd(&g_C[(rbase+1)*64 + cbase+3], (double)c13);
    atomicAdd(&g_C[(rbase+2)*64 + cbase+0], (double)c20);
    atomicAdd(&g_C[(rbase+2)*64 + cbase+1], (double)c21);
    atomicAdd(&g_C[(rbase+2)*64 + cbase+2], (double)c22);
    atomicAdd(&g_C[(rbase+2)*64 + cbase+3], (double)c23);
    atomicAdd(&g_C[(rbase+3)*64 + cbase+0], (double)c30);
    atomicAdd(&g_C[(rbase+3)*64 + cbase+1], (double)c31);
    atomicAdd(&g_C[(rbase+3)*64 + cbase+2], (double)c32);
    atomicAdd(&g_C[(rbase+3)*64 + cbase+3], (double)c33);
}

// ---------------------------------------------------------------------------
// Kernel 2: finalize per-channel BN params (unchanged)
// ---------------------------------------------------------------------------
__global__ void finalize_kernel(const float* __restrict__ W,
                                const float* __restrict__ gamma,
                                const float* __restrict__ beta) {
    __shared__ double s1[64];
    __shared__ double s2[64];
    const int d = blockIdx.x;
    const int p = threadIdx.x;

    double t1 = 0.0, t2 = 0.0;
    if (p < P_DIM) {
        double wp = (double)W[d * P_DIM + p];
        t1 = wp * g_colsum[p];
        double acc = 0.0;
        for (int q = 0; q < P_DIM; q++)
            acc += (double)W[d * P_DIM + q] * g_C[p * 64 + q];
        t2 = wp * acc;
    }
    s1[p] = t1; s2[p] = t2;
    __syncthreads();
    for (int s = 32; s > 0; s >>= 1) {
        if (p < s) { s1[p] += s1[p + s]; s2[p] += s2[p + s]; }
        __syncthreads();
    }
    if (p == 0) {
        const double inv = 1.0 / (double)M_TOTAL;
        double mean = s1[0] * inv;
        double var  = s2[0] * inv - mean * mean;
        float rsq = (float)(1.0 / sqrt(var + 1e-5));
        g_prm[d] = make_float4((float)mean, rsq, gamma[d], beta[d]);
    }
}

// ---------------------------------------------------------------------------
// mma.sync / ldmatrix / cp.async helpers (baseline PTX, plain sm_103 target)
// ---------------------------------------------------------------------------
__device__ __forceinline__ uint32_t smem_u32(const void* p) {
    uint32_t a;
    asm("{ .reg .u64 t; cvta.to.shared.u64 t, %1; cvt.u32.u64 %0, t; }"
        : "=r"(a) : "l"(p));
    return a;
}
#define LDSM4(r, addr) \
    asm volatile("ldmatrix.sync.aligned.m8n8.x4.shared.b16 {%0,%1,%2,%3}, [%4];" \
        : "=r"((r)[0]), "=r"((r)[1]), "=r"((r)[2]), "=r"((r)[3]) : "r"(addr))
#define LDSM4T(r, addr) \
    asm volatile("ldmatrix.sync.aligned.m8n8.x4.trans.shared.b16 {%0,%1,%2,%3}, [%4];" \
        : "=r"((r)[0]), "=r"((r)[1]), "=r"((r)[2]), "=r"((r)[3]) : "r"(addr))
#define MMA_BF16(d, a, bb0, bb1) \
    asm volatile("mma.sync.aligned.m16n8k16.row.col.f32.bf16.bf16.f32 " \
        "{%0,%1,%2,%3}, {%4,%5,%6,%7}, {%8,%9}, {%0,%1,%2,%3};" \
        : "+f"((d)[0]), "+f"((d)[1]), "+f"((d)[2]), "+f"((d)[3]) \
        : "r"((a)[0]), "r"((a)[1]), "r"((a)[2]), "r"((a)[3]), "r"(bb0), "r"(bb1))
__device__ __forceinline__ void cp_async16(uint32_t dst, const void* src) {
    asm volatile("{ .reg .u64 g; cvta.to.global.u64 g, %1; "
                 "cp.async.ca.shared.global [%0], [g], 16; }"
                 :: "r"(dst), "l"(src) : "memory");
}
#define CP_COMMIT() asm volatile("cp.async.commit_group;" ::: "memory")
#define CP_WAIT(n)  asm volatile("cp.async.wait_group %0;" :: "n"(n) : "memory")

// Exact scalar LIF trajectory (identical op order to the rel_err=0 kernel)
__device__ __noinline__ void lif_exact(const float* __restrict__ x,
                                       const float* __restrict__ W,
                                       float4 prm, int grow, int ch, int t,
                                       float& s_out, float& v_out) {
    float ve = 0.f;
    for (int tt = 0; tt <= t; tt++) {
        const float* xr = x + ((size_t)tt * BN_ROWS + grow) * P_DIM;
        float a = 0.f;
        for (int p = 0; p < P_DIM; p++)
            a = fmaf(xr[p], W[ch * P_DIM + p], a);
        float hh = (a - prm.x) * prm.y;
        hh = hh * prm.z + prm.w;
        float ve2 = ve + (hh - ve) * 0.5f;
        float se = ((ve2 - 1.0f) >= 0.0f) ? 1.0f : 0.0f;
        ve = ve2 * (1.0f - se);
        if (tt == t) { s_out = se; v_out = ve; }
    }
}

// ---------------------------------------------------------------------------
// Kernel 3: bf16 2-way-split tensor GEMM (mma.sync) + BN + 4-step LIF.
// cp.async double-buffered A pipeline: presplit bf16 x tiles stream into smem
// (coalesced 16B chunks) one full t-step ahead; compute phase touches only
// shared memory (LDSM4 A at 144B stride, LDSM4T B at 272B stride — both
// verified conflict-free + correct in earlier passing rounds). v (membrane)
// in registers; near-threshold (|v'-1| < 1e-3) elements take the exact scalar
// trajectory -> output identical to the rel_err=0 scalar kernel.
// ---------------------------------------------------------------------------
#define B_STRIDE   272                     // bytes per B row (136 bf16)
#define B_SPLIT_SZ (64 * B_STRIDE)         // 17408
#define A_STRIDE   144                     // bytes per A row (72 bf16)
#define A_SPLIT_SZ (64 * A_STRIDE)         // 9216
#define A_BUF_SZ   (2 * A_SPLIT_SZ)        // hi+lo = 18432
#define SM_B       0
#define SM_A       (2 * B_SPLIT_SZ)        // 34816
#define SM_TOTAL   (SM_A + 2 * A_BUF_SZ)   // 71680

__global__ __launch_bounds__(256, 2) void lif_mma_kernel(
    const float* __restrict__ x,
    const float* __restrict__ W,
    float* __restrict__ out) {
    extern __shared__ __align__(16) char smem[];
    const uint32_t sb = smem_u32(smem);
    const int tid  = threadIdx.x;
    const int wid  = tid >> 5;
    const int lane = tid & 31;
    const int m0   = (wid >> 1) * 16;      // warp's row offset in the 64-row tile
    const int wc   = (wid & 1) * 64;       // warp's channel offset (0 or 64)
    const int row0 = blockIdx.x * 64;

    // ---- stage W -> Bs[k][n], 2 bf16 splits (once per CTA)
    for (int i = tid; i < 64 * 128; i += 256) {
        int k = i >> 7, n = i & 127;
        float val = (k < P_DIM) ? W[n * P_DIM + k] : 0.f;
        uint16_t h = bfbits(val);
        uint16_t l = bfbits(val - bf2f(h));
        uint32_t off = (uint32_t)(k * B_STRIDE + n * 2);
        *(uint16_t*)(smem + SM_B + 0 * B_SPLIT_SZ + off) = h;
        *(uint16_t*)(smem + SM_B + 1 * B_SPLIT_SZ + off) = l;
    }

    // ---- cp.async issue helper (lambda): stream A splits for step tt
    auto issue_a = [&](int tt) {
        const uint32_t ab = sb + SM_A + (uint32_t)((tt & 1) * A_BUF_SZ);
        const char* srch = (const char*)g_xh + ((size_t)tt * BN_ROWS + row0) * 128;
        const char* srcl = (const char*)g_xl + ((size_t)tt * BN_ROWS + row0) * 128;
        #pragma unroll
        for (int j = 0; j < 4; j++) {
            int idx = tid + j * 256;           // 0..1023
            int sp  = idx >> 9;                // 0: hi, 1: lo
            int rc  = idx & 511;
            int r   = rc >> 3, c = rc & 7;     // row, 16B-chunk
            const char* s = (sp ? srcl : srch) + r * 128 + c * 16;
            cp_async16(ab + (uint32_t)(sp * A_SPLIT_SZ + r * A_STRIDE + c * 16), s);
        }
        CP_COMMIT();
    };

    issue_a(0);           // prologue prefetch (group G0)

    float v[8][4];
    #pragma unroll
    for (int i = 0; i < 8; i++)
        #pragma unroll
        for (int j = 0; j < 4; j++) v[i][j] = 0.f;

    const int arow  = m0 + (lane & 15);        // ldmatrix A lane addressing
    const int acolq = (lane >> 4) * 8;
    const int brow_ = lane & 15;               // ldmatrix B lane addressing
    const int bcolq = (lane >> 4) * 8;

    #pragma unroll
    for (int t = 0; t < T_STEPS; t++) {
        if (t < T_STEPS - 1) {                 // prefetch t+1, then wait for t
            issue_a(t + 1);
            CP_WAIT(1);
        } else {
            CP_WAIT(0);
        }
        __syncthreads();                       // A[t] visible (and W staged, t=0)

        const uint32_t abase = sb + SM_A + (uint32_t)((t & 1) * A_BUF_SZ);

        float acc[8][4];
        #pragma unroll
        for (int i = 0; i < 8; i++)
            #pragma unroll
            for (int j = 0; j < 4; j++) acc[i][j] = 0.f;

        #pragma unroll
        for (int kt = 0; kt < 4; kt++) {
            const int k0 = kt * 16;
            uint32_t a_off = abase + (uint32_t)(arow * A_STRIDE + (k0 + acolq) * 2);
            uint32_t ah[4], al[4];
            LDSM4(ah, a_off);
            LDSM4(al, a_off + (uint32_t)A_SPLIT_SZ);

            #pragma unroll
            for (int nc = 0; nc < 4; nc++) {
                const int n0 = wc + nc * 16;
                uint32_t b_off = sb + SM_B +
                    (uint32_t)((k0 + brow_) * B_STRIDE + (n0 + bcolq) * 2);
                uint32_t bh[4], bl[4];
                LDSM4T(bh, b_off);
                LDSM4T(bl, b_off + (uint32_t)B_SPLIT_SZ);

                float* d0 = acc[2 * nc];
                float* d1 = acc[2 * nc + 1];
                // small terms first: lo*hi, hi*lo, then hi*hi
                MMA_BF16(d0, al, bh[0], bh[1]);  MMA_BF16(d1, al, bh[2], bh[3]);
                MMA_BF16(d0, ah, bl[0], bl[1]);  MMA_BF16(d1, ah, bl[2], bl[3]);
                MMA_BF16(d0, ah, bh[0], bh[1]);  MMA_BF16(d1, ah, bh[2], bh[3]);
            }
        }

        // ---- BN + LIF epilogue (identical numerics to passing rounds)
        const int r0g = row0 + m0 + (lane >> 2);
        const int r1g = r0g + 8;
        #pragma unroll
        for (int nt = 0; nt < 8; nt++) {
            const int ch0 = wc + nt * 8 + 2 * (lane & 3);
            const float4 pa = g_prm[ch0];
            const float4 pb = g_prm[ch0 + 1];
            #pragma unroll
            for (int half = 0; half < 2; half++) {
                const int grow = half ? r1g : r0g;
                const int i0 = half * 2;
                float s0, s1;
                {   // channel ch0
                    float h = (acc[nt][i0] - pa.x) * pa.y;
                    h = h * pa.z + pa.w;
                    float vv = v[nt][i0] + (h - v[nt][i0]) * 0.5f;
                    s0 = ((vv - 1.0f) >= 0.0f) ? 1.0f : 0.0f;
                    float vr = vv * (1.0f - s0);
                    if (fabsf(vv - 1.0f) < 1e-3f)
                        lif_exact(x, W, pa, grow, ch0, t, s0, vr);
                    v[nt][i0] = vr;
                }
                {   // channel ch0+1
                    float h = (acc[nt][i0 + 1] - pb.x) * pb.y;
                    h = h * pb.z + pb.w;
                    float vv = v[nt][i0 + 1] + (h - v[nt][i0 + 1]) * 0.5f;
                    s1 = ((vv - 1.0f) >= 0.0f) ? 1.0f : 0.0f;
                    float vr = vv * (1.0f - s1);
                    if (fabsf(vv - 1.0f) < 1e-3f)
                        lif_exact(x, W, pb, grow, ch0 + 1, t, s1, vr);
                    v[nt][i0 + 1] = vr;
                }
                *(float2*)&out[((size_t)t * BN_ROWS + grow) * D_DIM + ch0] =
                    make_float2(s0, s1);
            }
        }
        __syncthreads();   // compute done before buffer (t+1 wrote other buf) reuse
    }
}

// ---------------------------------------------------------------------------
extern "C" void kernel_launch(void* const* d_in, const int* in_sizes, int n_in,
                              void* d_out, int out_size) {
    const float* x     = (const float*)d_in[0];   // [4,64,1024,63]
    const float* W     = (const float*)d_in[1];   // [128,63]
    const float* gamma = (const float*)d_in[2];   // [128]
    const float* beta  = (const float*)d_in[3];   // [128]
    float* out = (float*)d_out;                   // [4,64,1024,128]

    cudaFuncSetAttribute(lif_mma_kernel,
                         cudaFuncAttributeMaxDynamicSharedMemorySize, SM_TOTAL);

    zero_stats_kernel<<<16, 256>>>();
    stats_kernel<<<1024, 256>>>(x);
    finalize_kernel<<<D_DIM, 64>>>(W, gamma, beta);
    lif_mma_kernel<<<BN_ROWS / 64, 256, SM_TOTAL>>>(x, W, out);
}

// round 13
// speedup vs baseline: 1.3403x; 1.3403x over previous
#include <cuda_runtime.h>
#include <cstdint>

// Problem constants
#define T_STEPS  4
#define P_DIM    63
#define D_DIM    128
#define BN_ROWS  65536              // B*N = 64*1024
#define M_TOTAL  262144             // T*B*N
#define N_TILES  4096               // M_TOTAL / 64

// Scratch (no allocations allowed -> __device__ globals)
__device__ double g_C[64 * 64];     // S = sum_m x_m x_m^T  (col 63 zero-padded)
__device__ double g_colsum[64];     // per-feature column sums of x
__device__ float4 g_prm[D_DIM];     // per-channel (mean, rsqrt(var+eps), gamma, beta)
__device__ float  g_v[BN_ROWS * D_DIM];  // LIF membrane potential between t-steps

// ---------------------------------------------------------------------------
// Kernel 0: zero the stat accumulators (graph replays -> every launch)
// ---------------------------------------------------------------------------
__global__ void zero_stats_kernel() {
    int i = blockIdx.x * blockDim.x + threadIdx.x;
    if (i < 64 * 64) g_C[i] = 0.0;
    if (i < 64)      g_colsum[i] = 0.0;
}

// ---------------------------------------------------------------------------
// Kernel 1: stats pass.  S += X^T X  (upper triangle only, mirrored at flush)
// and colsum += X^T 1 over all M rows.
// 136 upper-triangle 4x4 tiles assigned warp-coherently to threads 0..135:
// warps 0-3 fully active, warp 4 partially, warps 5-7 skip the FMA loop ->
// ~0.63x warp-issue demand vs computing the full symmetric matrix.
// Per-tile partials are bit-identical to the full version (same products,
// same row order); fp64 atomic accumulation absorbs ordering differences.
// ---------------------------------------------------------------------------
__global__ __launch_bounds__(256) void stats_kernel(const float* __restrict__ x) {
    __shared__ __align__(16) float xs[64][64];
    const int tid = threadIdx.x;
    const int col = tid & 63;
    const int rg  = tid >> 6;

    // warp-coherent upper-triangle tile assignment (ti <= tj)
    const bool active = (tid < 136);
    int ti = 0, tj = 0;
    {
        int rem = active ? tid : 0;
        int r = 0;
        while (rem >= 16 - r) { rem -= 16 - r; r++; }
        ti = r;
        tj = r + rem;
    }

    float c00=0.f,c01=0.f,c02=0.f,c03=0.f;
    float c10=0.f,c11=0.f,c12=0.f,c13=0.f;
    float c20=0.f,c21=0.f,c22=0.f,c23=0.f;
    float c30=0.f,c31=0.f,c32=0.f,c33=0.f;
    float csum = 0.f;

    for (int tile = blockIdx.x; tile < N_TILES; tile += gridDim.x) {
        __syncthreads();
        const float* xb = x + (size_t)tile * (64 * 63);
        for (int i2 = tid; i2 < 64 * 64; i2 += 256) {
            int r = i2 >> 6, cc = i2 & 63;
            xs[r][cc] = (cc < 63) ? xb[r * 63 + cc] : 0.f;
        }
        __syncthreads();

        // column sums (4 threads per column, disjoint row sets)
        #pragma unroll 4
        for (int r = rg; r < 64; r += 4) csum += xs[r][col];

        // 4x4 outer-product accumulation (upper-triangle tiles only)
        if (active) {
            #pragma unroll 4
            for (int r = 0; r < 64; r++) {
                float4 a = *(const float4*)&xs[r][4 * ti];
                float4 b = *(const float4*)&xs[r][4 * tj];
                c00 = fmaf(a.x, b.x, c00); c01 = fmaf(a.x, b.y, c01);
                c02 = fmaf(a.x, b.z, c02); c03 = fmaf(a.x, b.w, c03);
                c10 = fmaf(a.y, b.x, c10); c11 = fmaf(a.y, b.y, c11);
                c12 = fmaf(a.y, b.z, c12); c13 = fmaf(a.y, b.w, c13);
                c20 = fmaf(a.z, b.x, c20); c21 = fmaf(a.z, b.y, c21);
                c22 = fmaf(a.z, b.z, c22); c23 = fmaf(a.z, b.w, c23);
                c30 = fmaf(a.w, b.x, c30); c31 = fmaf(a.w, b.y, c31);
                c32 = fmaf(a.w, b.z, c32); c33 = fmaf(a.w, b.w, c33);
            }
        }
    }

    // reduce colsum partials through smem (reuse xs rows 0..3)
    __syncthreads();
    xs[rg][col] = csum;
    __syncthreads();
    if (tid < 64) {
        float s = xs[0][tid] + xs[1][tid] + xs[2][tid] + xs[3][tid];
        atomicAdd(&g_colsum[tid], (double)s);
    }

    // flush 4x4 tile (and its mirror) to global S in fp64
    if (active) {
        const int rbase = 4 * ti, cbase = 4 * tj;
        const float cv[4][4] = {{c00,c01,c02,c03},{c10,c11,c12,c13},
                                {c20,c21,c22,c23},{c30,c31,c32,c33}};
        #pragma unroll
        for (int i = 0; i < 4; i++)
            #pragma unroll
            for (int j = 0; j < 4; j++) {
                atomicAdd(&g_C[(rbase + i) * 64 + (cbase + j)], (double)cv[i][j]);
                if (ti != tj)
                    atomicAdd(&g_C[(cbase + j) * 64 + (rbase + i)], (double)cv[i][j]);
            }
    }
}

// ---------------------------------------------------------------------------
// Kernel 2: finalize per-channel BN params from S and colsum. (unchanged)
// ---------------------------------------------------------------------------
__global__ void finalize_kernel(const float* __restrict__ W,
                                const float* __restrict__ gamma,
                                const float* __restrict__ beta) {
    __shared__ double s1[64];
    __shared__ double s2[64];
    const int d = blockIdx.x;
    const int p = threadIdx.x;

    double t1 = 0.0, t2 = 0.0;
    if (p < P_DIM) {
        double wp = (double)W[d * P_DIM + p];
        t1 = wp * g_colsum[p];
        double acc = 0.0;
        for (int q = 0; q < P_DIM; q++)
            acc += (double)W[d * P_DIM + q] * g_C[p * 64 + q];
        t2 = wp * acc;
    }
    s1[p] = t1; s2[p] = t2;
    __syncthreads();
    for (int s = 32; s > 0; s >>= 1) {
        if (p < s) { s1[p] += s1[p + s]; s2[p] += s2[p + s]; }
        __syncthreads();
    }
    if (p == 0) {
        const double inv = 1.0 / (double)M_TOTAL;
        double mean = s1[0] * inv;
        double var  = s2[0] * inv - mean * mean;
        float rsq = (float)(1.0 / sqrt(var + 1e-5));
        g_prm[d] = make_float4((float)mean, rsq, gamma[d], beta[d]);
    }
}

// ---------------------------------------------------------------------------
// Kernel 3: fused GEMM + BatchNorm + 4-step LIF. (byte-identical to the
// round-6 168us version: 128 threads, 8x8 scalar register tile, v in global
// scratch between t-steps so 4 CTAs / 16 warps fit per SM.)
// ---------------------------------------------------------------------------
__global__ __launch_bounds__(128, 4) void lif_main_kernel(
    const float* __restrict__ x,
    const float* __restrict__ W,
    float* __restrict__ out) {
    __shared__ __align__(16) float xs[64][65];     // 16.6 KB
    __shared__ __align__(16) float Wa[P_DIM][64];  // 15.75 KB  (ch 8g..8g+3)
    __shared__ __align__(16) float Wb[P_DIM][64];  // 15.75 KB  (ch 8g+4..8g+7)

    const int tid = threadIdx.x;
    const int tR = tid >> 4;     // 0..7  -> rows 8*tR .. 8*tR+7
    const int tC = tid & 15;     // 0..15 -> channels 8*tC .. 8*tC+7
    const int row0 = blockIdx.x * 64;

    // stage W: Wa[k][4g+j] = W[(8g+j)*63+k], Wb[k][4g+j] = W[(8g+4+j)*63+k]
    for (int i = tid; i < P_DIM * 64; i += 128) {
        int k = i >> 6, c = i & 63;
        int g = c >> 2, j = c & 3;
        Wa[k][c] = W[(8 * g + j)     * P_DIM + k];
        Wb[k][c] = W[(8 * g + 4 + j) * P_DIM + k];
    }

    for (int t = 0; t < T_STEPS; t++) {
        __syncthreads();  // also covers the W staging before first use
        const float* xb = x + ((size_t)t * BN_ROWS + row0) * P_DIM;
        for (int i2 = tid; i2 < 64 * P_DIM; i2 += 128) {
            int r = i2 / P_DIM, cc = i2 - r * P_DIM;
            xs[r][cc] = xb[i2];
        }
        __syncthreads();

        float acc[8][8];
        #pragma unroll
        for (int i = 0; i < 8; i++)
            #pragma unroll
            for (int j = 0; j < 8; j++) acc[i][j] = 0.f;

        #pragma unroll 1
        for (int k = 0; k < P_DIM; k++) {
            float4 b0 = *(const float4*)&Wa[k][4 * tC];
            float4 b1 = *(const float4*)&Wb[k][4 * tC];
            float a[8];
            #pragma unroll
            for (int i = 0; i < 8; i++) a[i] = xs[8 * tR + i][k];
            #pragma unroll
            for (int i = 0; i < 8; i++) {
                acc[i][0] = fmaf(a[i], b0.x, acc[i][0]);
                acc[i][1] = fmaf(a[i], b0.y, acc[i][1]);
                acc[i][2] = fmaf(a[i], b0.z, acc[i][2]);
                acc[i][3] = fmaf(a[i], b0.w, acc[i][3]);
                acc[i][4] = fmaf(a[i], b1.x, acc[i][4]);
                acc[i][5] = fmaf(a[i], b1.y, acc[i][5]);
                acc[i][6] = fmaf(a[i], b1.z, acc[i][6]);
                acc[i][7] = fmaf(a[i], b1.w, acc[i][7]);
            }
        }

        // BN + LIF epilogue; v round-trips through global scratch (bit-exact).
        #pragma unroll
        for (int i = 0; i < 8; i++) {
            const size_t vrow = (size_t)(row0 + 8 * tR + i) * D_DIM + 8 * tC;
            float v[8];
            if (t > 0) {
                float4 va = *(const float4*)&g_v[vrow];
                float4 vb = *(const float4*)&g_v[vrow + 4];
                v[0]=va.x; v[1]=va.y; v[2]=va.z; v[3]=va.w;
                v[4]=vb.x; v[5]=vb.y; v[6]=vb.z; v[7]=vb.w;
            } else {
                #pragma unroll
                for (int j = 0; j < 8; j++) v[j] = 0.f;
            }
            float sv[8];
            #pragma unroll
            for (int j = 0; j < 8; j++) {
                float4 prm = g_prm[8 * tC + j];     // (mean, rsq, gamma, beta)
                float h = (acc[i][j] - prm.x) * prm.y;
                h = h * prm.z + prm.w;
                float vv = v[j] + (h - v[j]) * 0.5f;              // v + (x-v)/tau
                float s = ((vv - 1.0f) >= 0.0f) ? 1.0f : 0.0f;    // H(v'-1)
                v[j] = vv * (1.0f - s);                           // hard reset
                sv[j] = s;
            }
            if (t < T_STEPS - 1) {
                *(float4*)&g_v[vrow]     = make_float4(v[0], v[1], v[2], v[3]);
                *(float4*)&g_v[vrow + 4] = make_float4(v[4], v[5], v[6], v[7]);
            }
            size_t o = ((size_t)t * BN_ROWS + row0 + 8 * tR + i) * D_DIM + 8 * tC;
            *(float4*)&out[o]     = make_float4(sv[0], sv[1], sv[2], sv[3]);
            *(float4*)&out[o + 4] = make_float4(sv[4], sv[5], sv[6], sv[7]);
        }
    }
}

// ---------------------------------------------------------------------------
extern "C" void kernel_launch(void* const* d_in, const int* in_sizes, int n_in,
                              void* d_out, int out_size) {
    const float* x     = (const float*)d_in[0];   // [4,64,1024,63]
    const float* W     = (const float*)d_in[1];   // [128,63]
    const float* gamma = (const float*)d_in[2];   // [128]
    const float* beta  = (const float*)d_in[3];   // [128]
    float* out = (float*)d_out;                   // [4,64,1024,128]

    zero_stats_kernel<<<16, 256>>>();
    stats_kernel<<<1024, 256>>>(x);
    finalize_kernel<<<D_DIM, 64>>>(W, gamma, beta);
    lif_main_kernel<<<BN_ROWS / 64, 128>>>(x, W, out);
}